// round 3
// baseline (speedup 1.0000x reference)
#include <cuda_runtime.h>
#include <math.h>

#define NB 4
#define Hh 64
#define Ff 10
#define Tt 60
#define Dd 6
#define Bb 2048

typedef unsigned long long ull;

// Packed recurrent weights: g_U4[j*64+h] = (U_i, U_ste, U_c, U_o)[j][h]
__device__ __align__(16) float4 g_U4[Hh * Hh];

__global__ void prep_kernel(const float* __restrict__ Ui, const float* __restrict__ Us,
                            const float* __restrict__ Uc, const float* __restrict__ Uo) {
    int idx = blockIdx.x * blockDim.x + threadIdx.x;
    if (idx < Hh * Hh) g_U4[idx] = make_float4(Ui[idx], Us[idx], Uc[idx], Uo[idx]);
}

__device__ __forceinline__ float hsig(float v) {
    return __saturatef(fmaf(v, 0.16666667f, 0.5f));
}
__device__ __forceinline__ ull pack2(float lo, float hi) {
    ull r; asm("mov.b64 %0, {%1, %2};" : "=l"(r) : "f"(lo), "f"(hi)); return r;
}
__device__ __forceinline__ ull fma2(ull a, ull b, ull c) {
    ull d; asm("fma.rn.f32x2 %0, %1, %2, %3;" : "=l"(d) : "l"(a), "l"(b), "l"(c)); return d;
}
__device__ __forceinline__ ull add2(ull a, ull b) {
    ull d; asm("add.rn.f32x2 %0, %1, %2;" : "=l"(d) : "l"(a), "l"(b)); return d;
}
__device__ __forceinline__ float2 unpack2(ull v) {
    float lo, hi; asm("mov.b64 {%0, %1}, %2;" : "=f"(lo), "=f"(hi) : "l"(v));
    return make_float2(lo, hi);
}

// Block = 128 threads: h = tid&63, half = tid>>6 owning j-range [32*half, 32*half+32)
// and batches {2*half, 2*half+1} for elementwise.
__global__ __launch_bounds__(2 * Hh) void sfm_kernel(
    const float* __restrict__ x,
    const float* __restrict__ W_i,   const float* __restrict__ b_i,
    const float* __restrict__ W_ste, const float* __restrict__ b_ste,
    const float* __restrict__ W_fre, const float* __restrict__ U_fre, const float* __restrict__ b_fre,
    const float* __restrict__ W_c,   const float* __restrict__ b_c,
    const float* __restrict__ W_o,   const float* __restrict__ b_o,
    const float* __restrict__ U_a,   const float* __restrict__ b_a,
    const float* __restrict__ W_p,   const float* __restrict__ b_p,
    float* __restrict__ out)
{
    __shared__ float sh_x[NB * Tt * Dd];
    __shared__ __align__(16) ull sh_h[Hh][NB];       // (h,h) dup pairs
    __shared__ __align__(16) ull sh_part[2][Hh][4];  // [writer_half][h][b2 is,co | b3 is,co]
    __shared__ float sh_frep[NB * Ff];               // half-1 fre partials
    __shared__ float sh_fre[NB][Ff];
    __shared__ float2 sh_cssn[Tt * Ff];
    __shared__ float sh_Ufre[Hh * Ff];

    const int tid  = threadIdx.x;
    const int h    = tid & (Hh - 1);
    const int half = tid >> 6;            // 0 or 1
    const int b0   = blockIdx.x * NB;
    const int ob0  = half * 2;            // first owned batch
    const int jbase = half * 32;

    const float* xg = x + (size_t)b0 * (Tt * Dd);
    for (int i = tid; i < NB * Tt * Dd; i += 2 * Hh) sh_x[i] = xg[i];
    for (int i = tid; i < Hh * Ff; i += 2 * Hh) sh_Ufre[i] = U_fre[i];
    for (int i = tid; i < Tt * Ff; i += 2 * Hh) {
        int tt = i / Ff + 1, f = i % Ff;
        int m  = (tt * f) % Ff;
        float ang = (float)m * 0.62831853071795864769f; // 2*pi/10
        float s, c; sincosf(ang, &s, &c);
        sh_cssn[i] = make_float2(c, s);
    }
    if (half == 0) {
#pragma unroll
        for (int b = 0; b < NB; b++) sh_h[h][b] = 0ull;
    }

    // Input weight columns for owned batches, packed (i,ste)/(c,o).
    ull wis[Dd], wco[Dd];
#pragma unroll
    for (int d = 0; d < Dd; d++) {
        wis[d] = pack2(W_i[d * Hh + h], W_ste[d * Hh + h]);
        wco[d] = pack2(W_c[d * Hh + h], W_o[d * Hh + h]);
    }
    const ull bias_is = pack2(b_i[h], b_ste[h]);
    const ull bias_co = pack2(b_c[h], b_o[h]);
    const float ba_ = b_a[h];
    float ua[Ff];
#pragma unroll
    for (int f = 0; f < Ff; f++) ua[f] = U_a[f];

    // fre duty: threads with h < 40 in BOTH halves compute partial j-sums.
    const bool fduty = (h < NB * Ff);
    const int  fb = h / Ff, ff = h % Ff;
    float wf[Dd]; float bf = 0.0f;
    if (fduty) {
#pragma unroll
        for (int d = 0; d < Dd; d++) wf[d] = W_fre[d * Ff + ff];
        bf = b_fre[ff];
    }

    // Oscillator state for the 2 owned batches.
    float sre[2][Ff], sim[2][Ff];
#pragma unroll
    for (int b = 0; b < 2; b++)
#pragma unroll
        for (int f = 0; f < Ff; f++) { sre[b][f] = 0.0f; sim[b][f] = 0.0f; }

    __syncthreads();

    const ulonglong2* U2 = reinterpret_cast<const ulonglong2*>(g_U4);

    for (int t = 0; t < Tt; t++) {
        // acc for all 4 batches; owned ones seeded with bias + x@W, others 0.
        ull acc_is[NB], acc_co[NB];
#pragma unroll
        for (int b = 0; b < NB; b++) { acc_is[b] = 0ull; acc_co[b] = 0ull; }
#pragma unroll
        for (int bl = 0; bl < 2; bl++) {
            int b = ob0 + bl;
            const float* xb = &sh_x[(b * Tt + t) * Dd];
            ull a0 = bias_is, a1 = bias_co;
#pragma unroll
            for (int d = 0; d < Dd; d++) {
                ull xd = pack2(xb[d], xb[d]);
                a0 = fma2(xd, wis[d], a0);
                a1 = fma2(xd, wco[d], a1);
            }
            acc_is[b] = a0; acc_co[b] = a1;
        }
        float af = 0.0f;
        if (fduty) {
            if (half == 0) {
                const float* xb = &sh_x[(fb * Tt + t) * Dd];
                af = bf;
#pragma unroll
                for (int d = 0; d < Dd; d++) af = fmaf(xb[d], wf[d], af);
            }
        }

        // K-split recurrent matmul: this half covers 32 j's.
#pragma unroll 16
        for (int jj = 0; jj < 32; jj++) {
            int j = jbase + jj;
            ulonglong2 u  = U2[j * Hh + h];                     // LDG.128 (L1-hot)
            ulonglong2 q0 = *(const ulonglong2*)&sh_h[j][0];    // b0,b1 (bcast)
            ulonglong2 q1 = *(const ulonglong2*)&sh_h[j][2];    // b2,b3
            acc_is[0] = fma2(q0.x, u.x, acc_is[0]);
            acc_co[0] = fma2(q0.x, u.y, acc_co[0]);
            acc_is[1] = fma2(q0.y, u.x, acc_is[1]);
            acc_co[1] = fma2(q0.y, u.y, acc_co[1]);
            acc_is[2] = fma2(q1.x, u.x, acc_is[2]);
            acc_co[2] = fma2(q1.x, u.y, acc_co[2]);
            acc_is[3] = fma2(q1.y, u.x, acc_is[3]);
            acc_co[3] = fma2(q1.y, u.y, acc_co[3]);
            if (fduty) {
                float hj = ((const float*)&sh_h[j][fb])[0];
                af = fmaf(hj, sh_Ufre[j * Ff + ff], af);
            }
        }

        // Publish partials for the batches the PEER finalizes.
        {
            int pb = (half ^ 1) * 2;  // peer's owned batches
            ull* dst = &sh_part[half][h][0];
            dst[0] = acc_is[pb];     dst[1] = acc_co[pb];
            dst[2] = acc_is[pb + 1]; dst[3] = acc_co[pb + 1];
        }
        if (fduty && half == 1) sh_frep[h] = af;
        __syncthreads();  // partials ready; all reads of sh_h done

        // Finalize fre (half 0 duty lanes), combining both halves.
        if (fduty && half == 0)
            sh_fre[fb][ff] = hsig(af + sh_frep[h]);

        // Combine gate partials for owned batches.
        ull my_is[2], my_co[2];
        {
            const ull* src = &sh_part[half ^ 1][h][0];
            my_is[0] = add2(acc_is[ob0],     src[0]);
            my_co[0] = add2(acc_co[ob0],     src[1]);
            my_is[1] = add2(acc_is[ob0 + 1], src[2]);
            my_co[1] = add2(acc_co[ob0 + 1], src[3]);
        }
        __syncthreads();  // sh_fre visible

        const float2* cssn = &sh_cssn[t * Ff];
#pragma unroll
        for (int bl = 0; bl < 2; bl++) {
            int b = ob0 + bl;
            float2 vis = unpack2(my_is[bl]);
            float2 vco = unpack2(my_co[bl]);
            float iv   = hsig(vis.x);
            float stev = hsig(vis.y);
            float ov   = hsig(vco.y);
            float cv   = iv * tanhf(vco.x);
            float acca = ba_;
#pragma unroll
            for (int f = 0; f < Ff; f++) {
                float fv = stev * sh_fre[b][f];
                float2 cn = cssn[f];
                float r = fmaf(fv, sre[bl][f], cv * cn.x);
                float m = fmaf(fv, sim[bl][f], cv * cn.y);
                sre[bl][f] = r;
                sim[bl][f] = m;
                acca = fmaf(fmaf(r, r, m * m), ua[f], acca);
            }
            float hv = ov * tanhf(acca);
            sh_h[h][b] = pack2(hv, hv);
        }
        __syncthreads();  // new h visible
    }

    // Projection: out[b] = h @ W_p + b_p (O = 1)
    if (tid < NB) {
        float acc = b_p[0];
#pragma unroll 8
        for (int j = 0; j < Hh; j++)
            acc = fmaf(((const float*)&sh_h[j][tid])[0], W_p[j], acc);
        out[b0 + tid] = acc;
    }
}

extern "C" void kernel_launch(void* const* d_in, const int* in_sizes, int n_in,
                              void* d_out, int out_size) {
    const float* x     = (const float*)d_in[0];
    const float* W_i   = (const float*)d_in[1];
    const float* U_i   = (const float*)d_in[2];
    const float* b_i   = (const float*)d_in[3];
    const float* W_ste = (const float*)d_in[4];
    const float* U_ste = (const float*)d_in[5];
    const float* b_ste = (const float*)d_in[6];
    const float* W_fre = (const float*)d_in[7];
    const float* U_fre = (const float*)d_in[8];
    const float* b_fre = (const float*)d_in[9];
    const float* W_c   = (const float*)d_in[10];
    const float* U_c   = (const float*)d_in[11];
    const float* b_c   = (const float*)d_in[12];
    const float* W_o   = (const float*)d_in[13];
    const float* U_o   = (const float*)d_in[14];
    const float* b_o   = (const float*)d_in[15];
    const float* U_a   = (const float*)d_in[16];
    const float* b_a   = (const float*)d_in[17];
    const float* W_p   = (const float*)d_in[18];
    const float* b_p   = (const float*)d_in[19];

    (void)in_sizes; (void)n_in; (void)out_size;

    prep_kernel<<<(Hh * Hh + 255) / 256, 256>>>(U_i, U_ste, U_c, U_o);
    sfm_kernel<<<Bb / NB, 2 * Hh>>>(x, W_i, b_i, W_ste, b_ste, W_fre, U_fre, b_fre,
                                    W_c, b_c, W_o, b_o, U_a, b_a, W_p, b_p,
                                    (float*)d_out);
}